// round 5
// baseline (speedup 1.0000x reference)
#include <cuda_runtime.h>

#define S_     16
#define IND    128
#define OD     64
#define ED     32
#define PN     4
#define ALPHA  0.8f

#define SN_STRIDE 132     // padded row stride (floats) for neigh tile
#define SE_STRIDE 36      // padded row stride (floats) for edge tile
#define SA_STRIDE 132     // padded row stride for agg tile

__device__ float g_wax[IND];     // W  @ a_x
__device__ float g_w2an[IND];    // W2 @ a_n

// ---------------------------------------------------------------------------
// K0: fold projection vectors — one warp per output element (256 warps)
// ---------------------------------------------------------------------------
__global__ __launch_bounds__(256) void precompute_kernel(
    const float* __restrict__ W,
    const float* __restrict__ W2,
    const float* __restrict__ a)
{
    int gw   = (blockIdx.x * blockDim.x + threadIdx.x) >> 5;
    int lane = threadIdx.x & 31;
    if (gw < 2 * IND) {
        int m = gw >> 7;
        int k = gw & (IND - 1);
        const float* Wm = m ? W2 : W;
        const float* av = m ? (a + OD) : a;
        float s = Wm[k * OD + lane] * av[lane]
                + Wm[k * OD + lane + 32] * av[lane + 32];
#pragma unroll
        for (int o = 16; o; o >>= 1) s += __shfl_down_sync(0xffffffffu, s, o);
        if (lane == 0) (m ? g_w2an : g_wax)[k] = s;
    }
}

// ---------------------------------------------------------------------------
// K1: fully fused persistent kernel
//     scores + softmax + aggregation + both projections, W/W2 in registers
// ---------------------------------------------------------------------------
__global__ __launch_bounds__(256, 2) void fused_kernel(
    const float* __restrict__ input,
    const float* __restrict__ neigh,
    const float* __restrict__ ee,
    const float* __restrict__ W,
    const float* __restrict__ W2,
    const float* __restrict__ a,
    float* __restrict__ out,
    int N, int ntiles)
{
    __shared__ float sN[PN * S_ * SN_STRIDE];     // 8448 f
    __shared__ float sE[PN * S_ * SE_STRIDE];     // 2304 f
    __shared__ float sIn[PN * IND];               // 512 f
    __shared__ float sAgg[PN * SA_STRIDE];        // 528 f
    __shared__ float sPart[2 * 4 * PN * OD];      // 2048 f  [mat][kg][p][d]
    __shared__ float sWax[IND];
    __shared__ float sW2an[IND];
    __shared__ float sAe[ED];
    __shared__ float sScore[PN * S_];
    __shared__ float sC[PN];

    const int tid = threadIdx.x;

    // --- per-block one-time setup -----------------------------------------
    const int d  = tid & 63;      // output dim within each 64-col matrix
    const int kg = tid >> 6;      // k-group: k = kg*32 .. kg*32+31

    float wreg[32], w2reg[32];
#pragma unroll
    for (int i = 0; i < 32; ++i) {
        wreg[i]  = W [(kg * 32 + i) * OD + d];
        w2reg[i] = W2[(kg * 32 + i) * OD + d];
    }
    if (tid < IND) { sWax[tid] = g_wax[tid]; sW2an[tid] = g_w2an[tid]; }
    if (tid < ED)  sAe[tid] = a[2 * OD + tid];

    // --- persistent tile loop ---------------------------------------------
    for (int tile = blockIdx.x; tile < ntiles; tile += gridDim.x) {
        const int n0 = tile * PN;

        // stage neigh tile: 64 rows x 128 f, padded rows of 33 float4
        {
            const float4* gN = (const float4*)(neigh + (size_t)n0 * S_ * IND);
            float4* s4 = (float4*)sN;
#pragma unroll
            for (int it = 0; it < 8; ++it) {
                int idx = tid + 256 * it;
                int r = idx >> 5, c = idx & 31;
                s4[r * 33 + c] = gN[idx];
            }
        }
        // stage edge tile: 64 rows x 32 f, padded rows of 9 float4
        {
            const float4* gE = (const float4*)(ee + (size_t)n0 * S_ * ED);
            float4* e4 = (float4*)sE;
#pragma unroll
            for (int it = 0; it < 2; ++it) {
                int idx = tid + 256 * it;
                int r = idx >> 3, c = idx & 7;
                e4[r * 9 + c] = gE[idx];
            }
        }
        // stage input rows: 512 f = 128 float4
        if (tid < 128)
            ((float4*)sIn)[tid] = ((const float4*)(input + (size_t)n0 * IND))[tid];

        __syncthreads();   // S1

        // c[p] = input_row . (W a_x)   — one warp per node
        if (tid < PN * 32) {
            int p = tid >> 5, l = tid & 31;
            float c = 0.f;
#pragma unroll
            for (int i = 0; i < IND / 32; ++i)
                c += sIn[p * IND + l + 32 * i] * sWax[l + 32 * i];
#pragma unroll
            for (int o = 16; o; o >>= 1) c += __shfl_down_sync(0xffffffffu, c, o);
            if (l == 0) sC[p] = c;
        }

        // raw scores: 64 (node,s) rows, 4 lanes each
        {
            int g = tid >> 2, j = tid & 3;
            float sc = 0.f;
            const float* nr = &sN[g * SN_STRIDE];
#pragma unroll
            for (int i = 0; i < IND / 4; ++i) sc += nr[j + 4 * i] * sW2an[j + 4 * i];
            const float* er = &sE[g * SE_STRIDE];
#pragma unroll
            for (int i = 0; i < ED / 4; ++i)  sc += er[j + 4 * i] * sAe[j + 4 * i];
            sc += __shfl_down_sync(0xffffffffu, sc, 2, 4);
            sc += __shfl_down_sync(0xffffffffu, sc, 1, 4);
            if (j == 0) sScore[g] = sc;
        }
        __syncthreads();   // S2

        // leaky-relu + softmax over S (one thread per node)
        if (tid < PN) {
            float c = sC[tid];
            float e[S_];
            float mx = -1e30f;
#pragma unroll
            for (int s = 0; s < S_; ++s) {
                float v = sScore[tid * S_ + s] + c;
                v = v > 0.f ? v : ALPHA * v;
                e[s] = v;
                mx = fmaxf(mx, v);
            }
            float sum = 0.f;
#pragma unroll
            for (int s = 0; s < S_; ++s) { e[s] = __expf(e[s] - mx); sum += e[s]; }
            float inv = 1.f / sum;
#pragma unroll
            for (int s = 0; s < S_; ++s) sScore[tid * S_ + s] = e[s] * inv;
        }
        __syncthreads();   // S3

        // aggregate raw neigh features -> sAgg
#pragma unroll
        for (int it = 0; it < 2; ++it) {
            int t = tid + 256 * it;
            int p = t >> 7, k = t & 127;
            float acc = 0.f;
#pragma unroll
            for (int s = 0; s < S_; ++s)
                acc += sScore[p * S_ + s] * sN[(p * S_ + s) * SN_STRIDE + k];
            sAgg[p * SA_STRIDE + k] = acc;
        }
        // aggregate edges -> out cols [128,160)
        if (tid < PN * ED) {
            int p = tid >> 5, e_ = tid & 31;
            float acc = 0.f;
#pragma unroll
            for (int s = 0; s < S_; ++s)
                acc += sScore[p * S_ + s] * sE[(p * S_ + s) * SE_STRIDE + e_];
            out[(size_t)(n0 + p) * 160 + 128 + e_] = acc;
        }
        __syncthreads();   // S4

        // projection partials: this thread's kg-slice of the k dimension
        // sPart layout: [mat][kg][p][d]
#pragma unroll
        for (int p = 0; p < PN; ++p) {
            const float4* xi = (const float4*)&sIn [p * IND       + kg * 32];
            const float4* xa = (const float4*)&sAgg[p * SA_STRIDE + kg * 32];
            float accW = 0.f, accA = 0.f;
#pragma unroll
            for (int q = 0; q < 8; ++q) {
                float4 vi = xi[q];
                float4 va = xa[q];
                accW += vi.x * wreg[q * 4 + 0] + vi.y * wreg[q * 4 + 1]
                      + vi.z * wreg[q * 4 + 2] + vi.w * wreg[q * 4 + 3];
                accA += va.x * w2reg[q * 4 + 0] + va.y * w2reg[q * 4 + 1]
                      + va.z * w2reg[q * 4 + 2] + va.w * w2reg[q * 4 + 3];
            }
            sPart[((0 * 4 + kg) * PN + p) * OD + d] = accW;
            sPart[((1 * 4 + kg) * PN + p) * OD + d] = accA;
        }
        __syncthreads();   // S5

        // reduce 4 kg-partials and store: 512 outputs, 2 per thread
#pragma unroll
        for (int it = 0; it < 2; ++it) {
            int o = tid + 256 * it;
            int p = o >> 7, c = o & 127;
            int mat = c >> 6, dd = c & 63;
            float v = sPart[((mat * 4 + 0) * PN + p) * OD + dd]
                    + sPart[((mat * 4 + 1) * PN + p) * OD + dd]
                    + sPart[((mat * 4 + 2) * PN + p) * OD + dd]
                    + sPart[((mat * 4 + 3) * PN + p) * OD + dd];
            out[(size_t)(n0 + p) * 160 + mat * 64 + dd] = v;
        }
        // no sync needed: next staging writes sN/sE/sIn, all readers done at S5;
        // sPart is not rewritten until after next S4.
    }
}

// ---------------------------------------------------------------------------
extern "C" void kernel_launch(void* const* d_in, const int* in_sizes, int n_in,
                              void* d_out, int out_size) {
    const float* input = (const float*)d_in[0];
    const float* neigh = (const float*)d_in[1];
    const float* ee    = (const float*)d_in[2];
    const float* W     = (const float*)d_in[3];
    const float* W2    = (const float*)d_in[4];
    const float* a     = (const float*)d_in[5];
    float* out = (float*)d_out;

    int N = in_sizes[0] / IND;      // 50000
    int ntiles = N / PN;            // 12500 (N divisible by 4)

    precompute_kernel<<<32, 256>>>(W, W2, a);
    fused_kernel<<<296, 256>>>(input, neigh, ee, W, W2, a, out, N, ntiles);
}

// round 9
// speedup vs baseline: 1.1571x; 1.1571x over previous
#include <cuda_runtime.h>

#define S_     16
#define IND    128
#define OD     64
#define ED     32
#define PN     4
#define ALPHA  0.8f

#define SN_STRIDE 132     // padded row stride (floats) for neigh tile (33 float4)
#define SE_STRIDE 36      // padded row stride (floats) for edge tile  (9 float4)
#define SA_STRIDE 132     // padded row stride for agg tile

// dynamic smem layout (float offsets)
#define OFF_N    0                      // 2 * 8448
#define OFF_E    16896                  // 2 * 2304
#define OFF_I    21504                  // 2 * 512
#define OFF_AGG  22528                  // 528
#define OFF_PART 23056                  // 2048
#define OFF_WAX  25104                  // 128
#define OFF_W2AN 25232                  // 128
#define OFF_AE   25360                  // 32
#define OFF_SC   25392                  // 64
#define OFF_C    25456                  // 4
#define SMEM_FLOATS 25460               // 101,840 bytes

__device__ float g_wax[IND];     // W  @ a_x
__device__ float g_w2an[IND];    // W2 @ a_n

__device__ __forceinline__ void cp16(float* s, const float4* g) {
    unsigned sa = (unsigned)__cvta_generic_to_shared(s);
    asm volatile("cp.async.cg.shared.global [%0], [%1], 16;" :: "r"(sa), "l"(g));
}
#define CP_COMMIT()  asm volatile("cp.async.commit_group;")
#define CP_WAIT(n)   asm volatile("cp.async.wait_group %0;" :: "n"(n))

// ---------------------------------------------------------------------------
// K0: fold projection vectors — one warp per output element (256 warps)
// ---------------------------------------------------------------------------
__global__ __launch_bounds__(256) void precompute_kernel(
    const float* __restrict__ W,
    const float* __restrict__ W2,
    const float* __restrict__ a)
{
    int gw   = (blockIdx.x * blockDim.x + threadIdx.x) >> 5;
    int lane = threadIdx.x & 31;
    if (gw < 2 * IND) {
        int m = gw >> 7;
        int k = gw & (IND - 1);
        const float* Wm = m ? W2 : W;
        const float* av = m ? (a + OD) : a;
        float s = Wm[k * OD + lane] * av[lane]
                + Wm[k * OD + lane + 32] * av[lane + 32];
#pragma unroll
        for (int o = 16; o; o >>= 1) s += __shfl_down_sync(0xffffffffu, s, o);
        if (lane == 0) (m ? g_w2an : g_wax)[k] = s;
    }
}

// ---------------------------------------------------------------------------
// K1: fused persistent kernel with cp.async double-buffered staging
// ---------------------------------------------------------------------------
__global__ __launch_bounds__(256, 2) void fused_kernel(
    const float* __restrict__ input,
    const float* __restrict__ neigh,
    const float* __restrict__ ee,
    const float* __restrict__ W,
    const float* __restrict__ W2,
    const float* __restrict__ a,
    float* __restrict__ out,
    int N, int ntiles)
{
    extern __shared__ float sm[];
    float* sAgg   = sm + OFF_AGG;
    float* sPart  = sm + OFF_PART;
    float* sWax   = sm + OFF_WAX;
    float* sW2an  = sm + OFF_W2AN;
    float* sAe    = sm + OFF_AE;
    float* sScore = sm + OFF_SC;
    float* sC     = sm + OFF_C;

    const int tid = threadIdx.x;
    const int d   = tid & 63;     // output dim within each 64-col matrix
    const int kg  = tid >> 6;     // k-group: k = kg*32 .. kg*32+31

    // one-time: W slices into registers, small vectors into shared
    float wreg[32], w2reg[32];
#pragma unroll
    for (int i = 0; i < 32; ++i) {
        wreg[i]  = W [(kg * 32 + i) * OD + d];
        w2reg[i] = W2[(kg * 32 + i) * OD + d];
    }
    if (tid < IND) { sWax[tid] = g_wax[tid]; sW2an[tid] = g_w2an[tid]; }
    if (tid < ED)  sAe[tid] = a[2 * OD + tid];

    // staging: issue cp.async for tile -> buffer buf
    auto stage = [&](int tile, int buf) {
        const int n0 = tile * PN;
        float* bN = sm + OFF_N + buf * (PN * S_ * SN_STRIDE);
        float* bE = sm + OFF_E + buf * (PN * S_ * SE_STRIDE);
        float* bI = sm + OFF_I + buf * (PN * IND);
        const float4* gN = (const float4*)(neigh + (size_t)n0 * S_ * IND);
#pragma unroll
        for (int it = 0; it < 8; ++it) {
            int idx = tid + 256 * it;
            int r = idx >> 5, c = idx & 31;
            cp16(bN + (r * 33 + c) * 4, gN + idx);
        }
        const float4* gE = (const float4*)(ee + (size_t)n0 * S_ * ED);
#pragma unroll
        for (int it = 0; it < 2; ++it) {
            int idx = tid + 256 * it;
            int r = idx >> 3, c = idx & 7;
            cp16(bE + (r * 9 + c) * 4, gE + idx);
        }
        if (tid < 128)
            cp16(bI + tid * 4, (const float4*)(input + (size_t)n0 * IND) + tid);
    };

    // prologue: prefetch first tile
    int buf = 0;
    stage(blockIdx.x, 0);
    CP_COMMIT();

    for (int tile = blockIdx.x; tile < ntiles; tile += gridDim.x) {
        const int n0  = tile * PN;
        const int nxt = tile + gridDim.x;

        if (nxt < ntiles) {
            stage(nxt, buf ^ 1);   // overlap next tile's DRAM fetch with compute
            CP_COMMIT();
            CP_WAIT(1);            // current tile's group complete
        } else {
            CP_WAIT(0);
        }
        __syncthreads();   // T1: current buffer visible to all

        float* bN = sm + OFF_N + buf * (PN * S_ * SN_STRIDE);
        float* bE = sm + OFF_E + buf * (PN * S_ * SE_STRIDE);
        float* bI = sm + OFF_I + buf * (PN * IND);

        // c[p] = input_row . (W a_x)   — one warp per node
        if (tid < PN * 32) {
            int p = tid >> 5, l = tid & 31;
            float c = 0.f;
#pragma unroll
            for (int i = 0; i < IND / 32; ++i)
                c += bI[p * IND + l + 32 * i] * sWax[l + 32 * i];
#pragma unroll
            for (int o = 16; o; o >>= 1) c += __shfl_down_sync(0xffffffffu, c, o);
            if (l == 0) sC[p] = c;
        }

        // raw scores: 64 (node,s) rows, 4 lanes each (conflict-free via padding)
        {
            int g = tid >> 2, j = tid & 3;
            float sc = 0.f;
            const float* nr = &bN[g * SN_STRIDE];
#pragma unroll
            for (int i = 0; i < IND / 4; ++i) sc += nr[j + 4 * i] * sW2an[j + 4 * i];
            const float* er = &bE[g * SE_STRIDE];
#pragma unroll
            for (int i = 0; i < ED / 4; ++i)  sc += er[j + 4 * i] * sAe[j + 4 * i];
            sc += __shfl_down_sync(0xffffffffu, sc, 2, 4);
            sc += __shfl_down_sync(0xffffffffu, sc, 1, 4);
            if (j == 0) sScore[g] = sc;
        }
        __syncthreads();   // S2

        // leaky-relu + softmax over S (one thread per node)
        if (tid < PN) {
            float c = sC[tid];
            float e[S_];
            float mx = -1e30f;
#pragma unroll
            for (int s = 0; s < S_; ++s) {
                float v = sScore[tid * S_ + s] + c;
                v = v > 0.f ? v : ALPHA * v;
                e[s] = v;
                mx = fmaxf(mx, v);
            }
            float sum = 0.f;
#pragma unroll
            for (int s = 0; s < S_; ++s) { e[s] = __expf(e[s] - mx); sum += e[s]; }
            float inv = 1.f / sum;
#pragma unroll
            for (int s = 0; s < S_; ++s) sScore[tid * S_ + s] = e[s] * inv;
        }
        __syncthreads();   // S3

        // aggregate raw neigh features -> sAgg
#pragma unroll
        for (int it = 0; it < 2; ++it) {
            int t = tid + 256 * it;
            int p = t >> 7, k = t & 127;
            float acc = 0.f;
#pragma unroll
            for (int s = 0; s < S_; ++s)
                acc += sScore[p * S_ + s] * bN[(p * S_ + s) * SN_STRIDE + k];
            sAgg[p * SA_STRIDE + k] = acc;
        }
        // aggregate edges -> out cols [128,160)
        if (tid < PN * ED) {
            int p = tid >> 5, e_ = tid & 31;
            float acc = 0.f;
#pragma unroll
            for (int s = 0; s < S_; ++s)
                acc += sScore[p * S_ + s] * bE[(p * S_ + s) * SE_STRIDE + e_];
            out[(size_t)(n0 + p) * 160 + 128 + e_] = acc;
        }
        __syncthreads();   // S4

        // projection partials: this thread's kg-slice of k  [mat][kg][p][d]
#pragma unroll
        for (int p = 0; p < PN; ++p) {
            const float4* xi = (const float4*)&bI  [p * IND       + kg * 32];
            const float4* xa = (const float4*)&sAgg[p * SA_STRIDE + kg * 32];
            float accW = 0.f, accA = 0.f;
#pragma unroll
            for (int q = 0; q < 8; ++q) {
                float4 vi = xi[q];
                float4 va = xa[q];
                accW += vi.x * wreg[q * 4 + 0] + vi.y * wreg[q * 4 + 1]
                      + vi.z * wreg[q * 4 + 2] + vi.w * wreg[q * 4 + 3];
                accA += va.x * w2reg[q * 4 + 0] + va.y * w2reg[q * 4 + 1]
                      + va.z * w2reg[q * 4 + 2] + va.w * w2reg[q * 4 + 3];
            }
            sPart[((0 * 4 + kg) * PN + p) * OD + d] = accW;
            sPart[((1 * 4 + kg) * PN + p) * OD + d] = accA;
        }
        __syncthreads();   // S5 — after this, no thread reads this tile's buffers

        // reduce 4 kg-partials and store: 512 outputs, 2 per thread
#pragma unroll
        for (int it = 0; it < 2; ++it) {
            int o = tid + 256 * it;
            int p = o >> 7, c = o & 127;
            int mat = c >> 6, dd = c & 63;
            float v = sPart[((mat * 4 + 0) * PN + p) * OD + dd]
                    + sPart[((mat * 4 + 1) * PN + p) * OD + dd]
                    + sPart[((mat * 4 + 2) * PN + p) * OD + dd]
                    + sPart[((mat * 4 + 3) * PN + p) * OD + dd];
            out[(size_t)(n0 + p) * 160 + mat * 64 + dd] = v;
        }

        buf ^= 1;
    }
}

// ---------------------------------------------------------------------------
extern "C" void kernel_launch(void* const* d_in, const int* in_sizes, int n_in,
                              void* d_out, int out_size) {
    const float* input = (const float*)d_in[0];
    const float* neigh = (const float*)d_in[1];
    const float* ee    = (const float*)d_in[2];
    const float* W     = (const float*)d_in[3];
    const float* W2    = (const float*)d_in[4];
    const float* a     = (const float*)d_in[5];
    float* out = (float*)d_out;

    int N = in_sizes[0] / IND;      // 50000
    int ntiles = N / PN;            // 12500

    static bool attr_set = false;
    if (!attr_set) {
        cudaFuncSetAttribute(fused_kernel,
                             cudaFuncAttributeMaxDynamicSharedMemorySize,
                             SMEM_FLOATS * (int)sizeof(float));
        attr_set = true;
    }

    precompute_kernel<<<32, 256>>>(W, W2, a);
    fused_kernel<<<296, 256, SMEM_FLOATS * sizeof(float)>>>(
        input, neigh, ee, W, W2, a, out, N, ntiles);
}

// round 12
// speedup vs baseline: 1.3117x; 1.1336x over previous
#include <cuda_runtime.h>

#define S_     16
#define IND    128
#define OD     64
#define ED     32
#define PN     4
#define ALPHA  0.8f

#define SN_STRIDE 144     // floats; 36 float4/row; 144 mod 32 = 16 -> conflict-free LDS.128
#define SE_STRIDE 48      // floats; 12 float4/row; 48 mod 32 = 16
#define SA_STRIDE 132

// dynamic smem layout (float offsets)
#define OFF_N    0                      // 2 * 64*144 = 18432
#define OFF_E    18432                  // 2 * 64*48  = 6144
#define OFF_I    24576                  // 2 * 512    = 1024
#define OFF_AGG  25600                  // 4*132 = 528
#define OFF_PART 26128                  // 2048  [mat][kg][p][d]
#define OFF_WAX  28176                  // 128
#define OFF_W2AN 28304                  // 128
#define OFF_AE   28432                  // 32
#define OFF_SC   28464                  // 64
#define OFF_C    28528                  // 16 (pad)
#define SMEM_FLOATS 28544               // 114,176 bytes -> 2 blocks/SM

__device__ float g_wax[IND];     // W  @ a_x
__device__ float g_w2an[IND];    // W2 @ a_n

__device__ __forceinline__ void cp16(float* s, const float4* g) {
    unsigned sa = (unsigned)__cvta_generic_to_shared(s);
    asm volatile("cp.async.cg.shared.global [%0], [%1], 16;" :: "r"(sa), "l"(g));
}
#define CP_COMMIT()  asm volatile("cp.async.commit_group;")
#define CP_WAIT(n)   asm volatile("cp.async.wait_group %0;" :: "n"(n))

__device__ __forceinline__ float dot4(float4 v, float4 w) {
    return v.x * w.x + v.y * w.y + v.z * w.z + v.w * w.w;
}

// ---------------------------------------------------------------------------
// K0: fold projection vectors
// ---------------------------------------------------------------------------
__global__ __launch_bounds__(256) void precompute_kernel(
    const float* __restrict__ W,
    const float* __restrict__ W2,
    const float* __restrict__ a)
{
    int gw   = (blockIdx.x * blockDim.x + threadIdx.x) >> 5;
    int lane = threadIdx.x & 31;
    if (gw < 2 * IND) {
        int m = gw >> 7;
        int k = gw & (IND - 1);
        const float* Wm = m ? W2 : W;
        const float* av = m ? (a + OD) : a;
        float s = Wm[k * OD + lane] * av[lane]
                + Wm[k * OD + lane + 32] * av[lane + 32];
#pragma unroll
        for (int o = 16; o; o >>= 1) s += __shfl_down_sync(0xffffffffu, s, o);
        if (lane == 0) (m ? g_w2an : g_wax)[k] = s;
    }
}

// ---------------------------------------------------------------------------
// K1: fused persistent kernel, cp.async double-buffered, LDS.128 everywhere
// ---------------------------------------------------------------------------
__global__ __launch_bounds__(256, 2) void fused_kernel(
    const float* __restrict__ input,
    const float* __restrict__ neigh,
    const float* __restrict__ ee,
    const float* __restrict__ W,
    const float* __restrict__ W2,
    const float* __restrict__ a,
    float* __restrict__ out,
    int N, int ntiles)
{
    extern __shared__ float sm[];
    float* sAgg   = sm + OFF_AGG;
    float* sPart  = sm + OFF_PART;
    float* sWax   = sm + OFF_WAX;
    float* sW2an  = sm + OFF_W2AN;
    float* sAe    = sm + OFF_AE;
    float* sScore = sm + OFF_SC;
    float* sC     = sm + OFF_C;

    const int tid = threadIdx.x;
    const int d   = tid & 63;     // output dim within each 64-col matrix
    const int kg  = tid >> 6;     // k-group: k = kg*32 .. kg*32+31

    float wreg[32], w2reg[32];
#pragma unroll
    for (int i = 0; i < 32; ++i) {
        wreg[i]  = W [(kg * 32 + i) * OD + d];
        w2reg[i] = W2[(kg * 32 + i) * OD + d];
    }
    if (tid < IND) { sWax[tid] = g_wax[tid]; sW2an[tid] = g_w2an[tid]; }
    if (tid < ED)  sAe[tid] = a[2 * OD + tid];

    auto stage = [&](int tile, int buf) {
        const int n0 = tile * PN;
        float* bN = sm + OFF_N + buf * (PN * S_ * SN_STRIDE);
        float* bE = sm + OFF_E + buf * (PN * S_ * SE_STRIDE);
        float* bI = sm + OFF_I + buf * (PN * IND);
        const float4* gN = (const float4*)(neigh + (size_t)n0 * S_ * IND);
#pragma unroll
        for (int it = 0; it < 8; ++it) {
            int idx = tid + 256 * it;
            int r = idx >> 5, c = idx & 31;
            cp16(bN + (r * 36 + c) * 4, gN + idx);
        }
        const float4* gE = (const float4*)(ee + (size_t)n0 * S_ * ED);
#pragma unroll
        for (int it = 0; it < 2; ++it) {
            int idx = tid + 256 * it;
            int r = idx >> 3, c = idx & 7;
            cp16(bE + (r * 12 + c) * 4, gE + idx);
        }
        if (tid < 128)
            cp16(bI + tid * 4, (const float4*)(input + (size_t)n0 * IND) + tid);
    };

    int buf = 0;
    stage(blockIdx.x, 0);
    CP_COMMIT();

    for (int tile = blockIdx.x; tile < ntiles; tile += gridDim.x) {
        const int n0  = tile * PN;
        const int nxt = tile + gridDim.x;

        if (nxt < ntiles) {
            stage(nxt, buf ^ 1);
            CP_COMMIT();
            CP_WAIT(1);
        } else {
            CP_WAIT(0);
        }
        __syncthreads();   // T1

        float* bN = sm + OFF_N + buf * (PN * S_ * SN_STRIDE);
        float* bE = sm + OFF_E + buf * (PN * S_ * SE_STRIDE);
        float* bI = sm + OFF_I + buf * (PN * IND);

        // c[p] = input_row . (W a_x) — one warp per node, 1 LDS.128/lane
        if (tid < PN * 32) {
            int p = tid >> 5, l = tid & 31;
            float c = dot4(((const float4*)(bI + p * IND))[l],
                           ((const float4*)sWax)[l]);
#pragma unroll
            for (int o = 16; o; o >>= 1) c += __shfl_down_sync(0xffffffffu, c, o);
            if (l == 0) sC[p] = c;
        }

        // raw scores: row g = p*S+s, 4 lanes each, LDS.128 (conflict-free padding)
        {
            int g = tid >> 2, jj = tid & 3;
            const float4* nr4 = (const float4*)(bN + g * SN_STRIDE);
            const float4* w4  = (const float4*)sW2an;
            float sc = 0.f;
#pragma unroll
            for (int i = 0; i < 8; ++i)
                sc += dot4(nr4[jj + 4 * i], w4[jj + 4 * i]);
            const float4* er4 = (const float4*)(bE + g * SE_STRIDE);
            const float4* a4  = (const float4*)sAe;
#pragma unroll
            for (int i = 0; i < 2; ++i)
                sc += dot4(er4[jj + 4 * i], a4[jj + 4 * i]);
            sc += __shfl_down_sync(0xffffffffu, sc, 2, 4);
            sc += __shfl_down_sync(0xffffffffu, sc, 1, 4);
            if (jj == 0) sScore[g] = sc;
        }
        __syncthreads();   // S2

        // softmax (4 threads) runs concurrently with input-proj partials (all)
        if (tid < PN) {
            float c = sC[tid];
            float e[S_];
            float mx = -1e30f;
#pragma unroll
            for (int s = 0; s < S_; ++s) {
                float v = sScore[tid * S_ + s] + c;
                v = v > 0.f ? v : ALPHA * v;
                e[s] = v;
                mx = fmaxf(mx, v);
            }
            float sum = 0.f;
#pragma unroll
            for (int s = 0; s < S_; ++s) { e[s] = __expf(e[s] - mx); sum += e[s]; }
            float inv = 1.f / sum;
#pragma unroll
            for (int s = 0; s < S_; ++s) sScore[tid * S_ + s] = e[s] * inv;
        }
        // input @ W partials (independent of scores): sPart[0][kg][p][d]
#pragma unroll
        for (int p = 0; p < PN; ++p) {
            const float4* xi = (const float4*)(bI + p * IND + kg * 32);
            float acc = 0.f;
#pragma unroll
            for (int q = 0; q < 8; ++q) {
                float4 v = xi[q];
                acc += v.x * wreg[q * 4 + 0] + v.y * wreg[q * 4 + 1]
                     + v.z * wreg[q * 4 + 2] + v.w * wreg[q * 4 + 3];
            }
            sPart[(kg * PN + p) * OD + d] = acc;
        }
        __syncthreads();   // S3

        // aggregation: warps 0-3 neigh (float4), warps 4-7 edges (+store)
        if (tid < 128) {
            int p = tid >> 5, q = tid & 31;
            const float* att = sScore + p * S_;
            float4 acc = make_float4(0.f, 0.f, 0.f, 0.f);
#pragma unroll
            for (int s = 0; s < S_; ++s) {
                float4 v = ((const float4*)(bN + (p * S_ + s) * SN_STRIDE))[q];
                float w = att[s];
                acc.x += w * v.x; acc.y += w * v.y;
                acc.z += w * v.z; acc.w += w * v.w;
            }
            ((float4*)(sAgg + p * SA_STRIDE))[q] = acc;
        } else {
            int t = tid - 128;
            int p = t >> 5, e_ = t & 31;
            const float* att = sScore + p * S_;
            float acc = 0.f;
#pragma unroll
            for (int s = 0; s < S_; ++s)
                acc += att[s] * bE[(p * S_ + s) * SE_STRIDE + e_];
            out[(size_t)(n0 + p) * 160 + 128 + e_] = acc;
        }
        __syncthreads();   // S4

        // agg @ W2 partials: sPart[1][kg][p][d]
#pragma unroll
        for (int p = 0; p < PN; ++p) {
            const float4* xa = (const float4*)(sAgg + p * SA_STRIDE + kg * 32);
            float acc = 0.f;
#pragma unroll
            for (int q = 0; q < 8; ++q) {
                float4 v = xa[q];
                acc += v.x * w2reg[q * 4 + 0] + v.y * w2reg[q * 4 + 1]
                     + v.z * w2reg[q * 4 + 2] + v.w * w2reg[q * 4 + 3];
            }
            sPart[1024 + (kg * PN + p) * OD + d] = acc;
        }
        __syncthreads();   // S5

        // reduce 4 kg-partials and store: 512 outputs, 2 per thread
#pragma unroll
        for (int it = 0; it < 2; ++it) {
            int o = tid + 256 * it;
            int p = o >> 7, c = o & 127;
            int mat = c >> 6, dd = c & 63;
            const float* b = sPart + mat * 1024 + p * OD + dd;
            float v = b[0] + b[256] + b[512] + b[768];
            out[(size_t)(n0 + p) * 160 + mat * 64 + dd] = v;
        }

        buf ^= 1;
    }
}

// ---------------------------------------------------------------------------
extern "C" void kernel_launch(void* const* d_in, const int* in_sizes, int n_in,
                              void* d_out, int out_size) {
    const float* input = (const float*)d_in[0];
    const float* neigh = (const float*)d_in[1];
    const float* ee    = (const float*)d_in[2];
    const float* W     = (const float*)d_in[3];
    const float* W2    = (const float*)d_in[4];
    const float* a     = (const float*)d_in[5];
    float* out = (float*)d_out;

    int N = in_sizes[0] / IND;      // 50000
    int ntiles = N / PN;            // 12500

    static bool attr_set = false;
    if (!attr_set) {
        cudaFuncSetAttribute(fused_kernel,
                             cudaFuncAttributeMaxDynamicSharedMemorySize,
                             SMEM_FLOATS * (int)sizeof(float));
        attr_set = true;
    }

    precompute_kernel<<<32, 256>>>(W, W2, a);
    fused_kernel<<<296, 256, SMEM_FLOATS * sizeof(float)>>>(
        input, neigh, ee, W, W2, a, out, N, ntiles);
}

// round 13
// speedup vs baseline: 1.4888x; 1.1350x over previous
#include <cuda_runtime.h>

#define S_     16
#define IND    128
#define OD     64
#define ED     32
#define PN     4
#define ALPHA  0.8f

#define SN_STRIDE 144     // floats; 36 float4/row; conflict-free LDS.128
#define SE_STRIDE 48      // floats; 12 float4/row
#define SA_STRIDE 132

// dynamic smem layout (float offsets)
#define OFF_N    0                      // 2 * 64*144 = 18432
#define OFF_E    18432                  // 2 * 64*48  = 6144
#define OFF_I    24576                  // 2 * 512    = 1024
#define OFF_AGG  25600                  // 4*132 = 528
#define OFF_PART 26128                  // 2048  [kg8][p][d] (reused mat0 then mat1)
#define OFF_WAX  28176                  // 128
#define OFF_W2AN 28304                  // 128
#define OFF_AE   28432                  // 32
#define OFF_SC   28464                  // 64
#define OFF_C    28528                  // 16 (pad)
#define SMEM_FLOATS 28544               // 114,176 bytes -> 2 blocks/SM

__device__ float g_wax[IND];     // W  @ a_x
__device__ float g_w2an[IND];    // W2 @ a_n

__device__ __forceinline__ void cp16(float* s, const float4* g) {
    unsigned sa = (unsigned)__cvta_generic_to_shared(s);
    asm volatile("cp.async.cg.shared.global [%0], [%1], 16;" :: "r"(sa), "l"(g));
}
#define CP_COMMIT()  asm volatile("cp.async.commit_group;")
#define CP_WAIT(n)   asm volatile("cp.async.wait_group %0;" :: "n"(n))

__device__ __forceinline__ float dot4(float4 v, float4 w) {
    return v.x * w.x + v.y * w.y + v.z * w.z + v.w * w.w;
}
// packed fp32x2 FMA: d = a*b + d on two packed floats
__device__ __forceinline__ void ffma2(unsigned long long& d,
                                      unsigned long long a,
                                      unsigned long long b) {
    asm("fma.rn.f32x2 %0, %1, %2, %0;" : "+l"(d) : "l"(a), "l"(b));
}
__device__ __forceinline__ unsigned long long splat2(float x) {
    unsigned long long r;
    asm("mov.b64 %0, {%1, %1};" : "=l"(r) : "f"(x));
    return r;
}
__device__ __forceinline__ unsigned long long packf2(float lo, float hi) {
    unsigned long long r;
    asm("mov.b64 %0, {%1, %2};" : "=l"(r) : "f"(lo), "f"(hi));
    return r;
}

// ---------------------------------------------------------------------------
// K0: fold projection vectors
// ---------------------------------------------------------------------------
__global__ __launch_bounds__(256) void precompute_kernel(
    const float* __restrict__ W,
    const float* __restrict__ W2,
    const float* __restrict__ a)
{
    int gw   = (blockIdx.x * blockDim.x + threadIdx.x) >> 5;
    int lane = threadIdx.x & 31;
    if (gw < 2 * IND) {
        int m = gw >> 7;
        int k = gw & (IND - 1);
        const float* Wm = m ? W2 : W;
        const float* av = m ? (a + OD) : a;
        float s = Wm[k * OD + lane] * av[lane]
                + Wm[k * OD + lane + 32] * av[lane + 32];
#pragma unroll
        for (int o = 16; o; o >>= 1) s += __shfl_down_sync(0xffffffffu, s, o);
        if (lane == 0) (m ? g_w2an : g_wax)[k] = s;
    }
}

// ---------------------------------------------------------------------------
// K1: fused persistent kernel; cp.async DB; f32x2 projection math
// ---------------------------------------------------------------------------
__global__ __launch_bounds__(256, 2) void fused_kernel(
    const float* __restrict__ input,
    const float* __restrict__ neigh,
    const float* __restrict__ ee,
    const float* __restrict__ W,
    const float* __restrict__ W2,
    const float* __restrict__ a,
    float* __restrict__ out,
    int N, int ntiles)
{
    extern __shared__ float sm[];
    float* sAgg   = sm + OFF_AGG;
    float* sPart  = sm + OFF_PART;
    float* sWax   = sm + OFF_WAX;
    float* sW2an  = sm + OFF_W2AN;
    float* sAe    = sm + OFF_AE;
    float* sScore = sm + OFF_SC;
    float* sC     = sm + OFF_C;

    const int tid = threadIdx.x;
    const int dp  = tid & 31;     // d-pair: d = 2dp, 2dp+1
    const int kg8 = tid >> 5;     // k-group: k = kg8*16 .. kg8*16+15

    // packed weight pairs: wp[i] = (W[k][2dp], W[k][2dp+1]), k = kg8*16+i
    unsigned long long wp[16], w2p[16];
#pragma unroll
    for (int i = 0; i < 16; ++i) {
        const float* w1 = &W [(kg8 * 16 + i) * OD + 2 * dp];
        const float* w2 = &W2[(kg8 * 16 + i) * OD + 2 * dp];
        wp[i]  = packf2(w1[0], w1[1]);
        w2p[i] = packf2(w2[0], w2[1]);
    }
    if (tid < IND) { sWax[tid] = g_wax[tid]; sW2an[tid] = g_w2an[tid]; }
    if (tid < ED)  sAe[tid] = a[2 * OD + tid];

    auto stage = [&](int tile, int buf) {
        const int n0 = tile * PN;
        float* bN = sm + OFF_N + buf * (PN * S_ * SN_STRIDE);
        float* bE = sm + OFF_E + buf * (PN * S_ * SE_STRIDE);
        float* bI = sm + OFF_I + buf * (PN * IND);
        const float4* gN = (const float4*)(neigh + (size_t)n0 * S_ * IND);
#pragma unroll
        for (int it = 0; it < 8; ++it) {
            int idx = tid + 256 * it;
            int r = idx >> 5, c = idx & 31;
            cp16(bN + (r * 36 + c) * 4, gN + idx);
        }
        const float4* gE = (const float4*)(ee + (size_t)n0 * S_ * ED);
#pragma unroll
        for (int it = 0; it < 2; ++it) {
            int idx = tid + 256 * it;
            int r = idx >> 3, c = idx & 7;
            cp16(bE + (r * 12 + c) * 4, gE + idx);
        }
        if (tid < 128)
            cp16(bI + tid * 4, (const float4*)(input + (size_t)n0 * IND) + tid);
    };

    int buf = 0;
    stage(blockIdx.x, 0);
    CP_COMMIT();

    for (int tile = blockIdx.x; tile < ntiles; tile += gridDim.x) {
        const int n0  = tile * PN;
        const int nxt = tile + gridDim.x;

        if (nxt < ntiles) {
            stage(nxt, buf ^ 1);
            CP_COMMIT();
            CP_WAIT(1);
        } else {
            CP_WAIT(0);
        }
        __syncthreads();   // T1

        float* bN = sm + OFF_N + buf * (PN * S_ * SN_STRIDE);
        float* bE = sm + OFF_E + buf * (PN * S_ * SE_STRIDE);
        float* bI = sm + OFF_I + buf * (PN * IND);

        // c[p] = input_row . (W a_x) — one warp per node
        if (tid < PN * 32) {
            int p = tid >> 5, l = tid & 31;
            float c = dot4(((const float4*)(bI + p * IND))[l],
                           ((const float4*)sWax)[l]);
#pragma unroll
            for (int o = 16; o; o >>= 1) c += __shfl_down_sync(0xffffffffu, c, o);
            if (l == 0) sC[p] = c;
        }

        // raw scores: row g = p*S+s, 4 lanes each, LDS.128
        {
            int g = tid >> 2, jj = tid & 3;
            const float4* nr4 = (const float4*)(bN + g * SN_STRIDE);
            const float4* w4  = (const float4*)sW2an;
            float sc = 0.f;
#pragma unroll
            for (int i = 0; i < 8; ++i)
                sc += dot4(nr4[jj + 4 * i], w4[jj + 4 * i]);
            const float4* er4 = (const float4*)(bE + g * SE_STRIDE);
            const float4* a4  = (const float4*)sAe;
#pragma unroll
            for (int i = 0; i < 2; ++i)
                sc += dot4(er4[jj + 4 * i], a4[jj + 4 * i]);
            sc += __shfl_down_sync(0xffffffffu, sc, 2, 4);
            sc += __shfl_down_sync(0xffffffffu, sc, 1, 4);
            if (jj == 0) sScore[g] = sc;
        }
        __syncthreads();   // S2

        // softmax (4 threads) runs concurrently with input@W partials (all)
        if (tid < PN) {
            float c = sC[tid];
            float e[S_];
            float mx = -1e30f;
#pragma unroll
            for (int s = 0; s < S_; ++s) {
                float v = sScore[tid * S_ + s] + c;
                v = v > 0.f ? v : ALPHA * v;
                e[s] = v;
                mx = fmaxf(mx, v);
            }
            float sum = 0.f;
#pragma unroll
            for (int s = 0; s < S_; ++s) { e[s] = __expf(e[s] - mx); sum += e[s]; }
            float inv = 1.f / sum;
#pragma unroll
            for (int s = 0; s < S_; ++s) sScore[tid * S_ + s] = e[s] * inv;
        }
        // input @ W partials (f32x2): sPart[kg8][p][d-pair]
#pragma unroll
        for (int p = 0; p < PN; ++p) {
            const float4* xi = (const float4*)(bI + p * IND + kg8 * 16);
            unsigned long long acc = 0ull;
#pragma unroll
            for (int q = 0; q < 4; ++q) {
                float4 v = xi[q];
                ffma2(acc, wp[q * 4 + 0], splat2(v.x));
                ffma2(acc, wp[q * 4 + 1], splat2(v.y));
                ffma2(acc, wp[q * 4 + 2], splat2(v.z));
                ffma2(acc, wp[q * 4 + 3], splat2(v.w));
            }
            *(unsigned long long*)&sPart[(kg8 * PN + p) * OD + 2 * dp] = acc;
        }
        __syncthreads();   // S3

        // warps 0-3: neigh aggregation (float4)
        if (tid < 128) {
            int p = tid >> 5, q = tid & 31;
            const float* att = sScore + p * S_;
            float4 acc = make_float4(0.f, 0.f, 0.f, 0.f);
#pragma unroll
            for (int s = 0; s < S_; ++s) {
                float4 v = ((const float4*)(bN + (p * S_ + s) * SN_STRIDE))[q];
                float w = att[s];
                acc.x += w * v.x; acc.y += w * v.y;
                acc.z += w * v.z; acc.w += w * v.w;
            }
            ((float4*)(sAgg + p * SA_STRIDE))[q] = acc;
        } else {
            // warps 4-7: edge aggregation + mat0 (input@W) reduce+store
            int t = tid - 128;
            int p = t >> 5, e_ = t & 31;
            const float* att = sScore + p * S_;
            float acc = 0.f;
#pragma unroll
            for (int s = 0; s < S_; ++s)
                acc += att[s] * bE[(p * S_ + s) * SE_STRIDE + e_];
            out[(size_t)(n0 + p) * 160 + 128 + e_] = acc;

            // reduce mat0: 128 threads, one d-pair each: (p2, dp2)
            int p2 = t >> 5, dp2 = t & 31;
            float2 v = make_float2(0.f, 0.f);
#pragma unroll
            for (int kg = 0; kg < 8; ++kg) {
                float2 u = *(const float2*)&sPart[(kg * PN + p2) * OD + 2 * dp2];
                v.x += u.x; v.y += u.y;
            }
            *(float2*)&out[(size_t)(n0 + p2) * 160 + 2 * dp2] = v;
        }
        __syncthreads();   // S4 — mat0 partials consumed; sPart reusable

        // agg @ W2 partials (f32x2) into the SAME sPart region
#pragma unroll
        for (int p = 0; p < PN; ++p) {
            const float4* xa = (const float4*)(sAgg + p * SA_STRIDE + kg8 * 16);
            unsigned long long acc = 0ull;
#pragma unroll
            for (int q = 0; q < 4; ++q) {
                float4 v = xa[q];
                ffma2(acc, w2p[q * 4 + 0], splat2(v.x));
                ffma2(acc, w2p[q * 4 + 1], splat2(v.y));
                ffma2(acc, w2p[q * 4 + 2], splat2(v.z));
                ffma2(acc, w2p[q * 4 + 3], splat2(v.w));
            }
            *(unsigned long long*)&sPart[(kg8 * PN + p) * OD + 2 * dp] = acc;
        }
        __syncthreads();   // S5

        // reduce mat1 and store: 128 threads, one d-pair each
        if (tid < 128) {
            int p = tid >> 5, dp2 = tid & 31;
            float2 v = make_float2(0.f, 0.f);
#pragma unroll
            for (int kg = 0; kg < 8; ++kg) {
                float2 u = *(const float2*)&sPart[(kg * PN + p) * OD + 2 * dp2];
                v.x += u.x; v.y += u.y;
            }
            *(float2*)&out[(size_t)(n0 + p) * 160 + 64 + 2 * dp2] = v;
        }

        buf ^= 1;
    }
}

// ---------------------------------------------------------------------------
extern "C" void kernel_launch(void* const* d_in, const int* in_sizes, int n_in,
                              void* d_out, int out_size) {
    const float* input = (const float*)d_in[0];
    const float* neigh = (const float*)d_in[1];
    const float* ee    = (const float*)d_in[2];
    const float* W     = (const float*)d_in[3];
    const float* W2    = (const float*)d_in[4];
    const float* a     = (const float*)d_in[5];
    float* out = (float*)d_out;

    int N = in_sizes[0] / IND;      // 50000
    int ntiles = N / PN;            // 12500

    static bool attr_set = false;
    if (!attr_set) {
        cudaFuncSetAttribute(fused_kernel,
                             cudaFuncAttributeMaxDynamicSharedMemorySize,
                             SMEM_FLOATS * (int)sizeof(float));
        attr_set = true;
    }

    precompute_kernel<<<32, 256>>>(W, W2, a);
    fused_kernel<<<296, 256, SMEM_FLOATS * sizeof(float)>>>(
        input, neigh, ee, W, W2, a, out, N, ntiles);
}